// round 15
// baseline (speedup 1.0000x reference)
#include <cuda_runtime.h>
#include <cuda_fp16.h>
#include <cstdint>

#define N_NODES_MAX 100032
#define IN_FEATS    256
#define OUT_FEATS   64
#define H_PITCH     32          // 32 x half2 per node row (64 fp16 feats)
#define CAP         64          // fixed bucket capacity (P(deg>=64) ~ 1e-18)

// Scratch (all __device__ globals, no allocation). g_count relies on CUDA's
// zero-initialization; the aggregate kernel restores it to all-zero after
// every use (self-resetting invariant across graph replays).
__device__ unsigned g_h16[(size_t)N_NODES_MAX * H_PITCH];   // h in half2 pairs
__device__ int      g_count[N_NODES_MAX];
__device__ int2     g_edge[(size_t)N_NODES_MAX * CAP];      // {src, w_bits}
__device__ unsigned g_wk[(IN_FEATS / 2) * OUT_FEATS];       // W kword-packed fp16

// ---------------------------------------------------------------------------
// helpers
// ---------------------------------------------------------------------------
__device__ __forceinline__ unsigned pack_h2(float a, float b) {
    __half2 h = __floats2half2_rn(a, b);
    return *(unsigned*)&h;
}

__device__ __forceinline__ void cp16(void* smem_dst, const void* gsrc) {
    unsigned d = (unsigned)__cvta_generic_to_shared(smem_dst);
    asm volatile("cp.async.ca.shared.global [%0], [%1], 16;"
                 :: "r"(d), "l"(gsrc));
}
#define CP_COMMIT() asm volatile("cp.async.commit_group;")
#define CP_WAIT1()  asm volatile("cp.async.wait_group 1;")
#define CP_WAIT0()  asm volatile("cp.async.wait_group 0;")

#define MMA_F16(d, a, b)                                                      \
    asm volatile(                                                             \
        "mma.sync.aligned.m16n8k16.row.col.f32.f16.f16.f32 "                  \
        "{%0,%1,%2,%3}, {%4,%5,%6,%7}, {%8,%9}, {%0,%1,%2,%3};"               \
        : "+f"(d[0]), "+f"(d[1]), "+f"(d[2]), "+f"(d[3])                      \
        : "r"(a[0]), "r"(a[1]), "r"(a[2]), "r"(a[3]), "r"(b[0]), "r"(b[1]))

// ---------------------------------------------------------------------------
// W pre-pack: wk[kr][n] = half2{ w[2kr][n], w[2kr+1][n] }  (kword layout,
// exactly the B-fragment word the MMA consumes).
// ---------------------------------------------------------------------------
__global__ void wconvert_kernel(const float* __restrict__ w,
                                unsigned* __restrict__ wk)
{
    int i = blockIdx.x * blockDim.x + threadIdx.x;   // 0 .. 8191
    if (i >= (IN_FEATS / 2) * OUT_FEATS) return;
    int kr = i >> 6;
    int n  = i & 63;
    wk[i] = pack_h2(w[(size_t)(2 * kr) * OUT_FEATS + n],
                    w[(size_t)(2 * kr + 1) * OUT_FEATS + n]);
}

// ---------------------------------------------------------------------------
// GEMM: h16[n,64] = fp16(x[n,256] @ W[256,64]), fp16 MMA.
// x: cp.async double-buffered fp32 staging, inline cvt at fragment load.
// W: cp.async double-buffered kword-fp16 tiles from g_wk.
// Block: 128M x 64N, 256 threads = 8 warps (4x2), warp tile 32x32.
// ---------------------------------------------------------------------------
#define BM 128
#define BK 32
#define SXP 36   // x staging pitch (floats): 16B-aligned rows, <=2-way banks
#define SWP 68   // wk tile pitch (words):    16B-aligned rows, <=2-way banks

__global__ __launch_bounds__(256) void gemm_f16_kernel(
    const float* __restrict__ x, const unsigned* __restrict__ wk,
    unsigned* __restrict__ h16, int n_rows)
{
    __shared__ float    sx[2][BM][SXP];
    __shared__ unsigned sw[2][16][SWP];

    const int tid    = threadIdx.x;
    const int lane   = tid & 31;
    const int wid    = tid >> 5;
    const int warp_m = wid >> 1;
    const int warp_n = wid & 1;
    const int lq     = lane >> 2;
    const int lr     = lane & 3;
    const int row0   = blockIdx.x * BM;

    float acc[2][4][4];
#pragma unroll
    for (int mt = 0; mt < 2; mt++)
#pragma unroll
        for (int nt = 0; nt < 4; nt++)
#pragma unroll
            for (int r = 0; r < 4; r++) acc[mt][nt][r] = 0.f;

    // async issue of tile t into buffer buf
    auto issue = [&](int t, int buf) {
        // x tile: 128 rows x 32 k fp32 = 1024 float4, 4 per thread
#pragma unroll
        for (int it = 0; it < 4; it++) {
            int idx = it * 256 + tid;
            int r   = idx >> 3;
            int q   = idx & 7;
            int row = min(row0 + r, n_rows - 1);   // clamp; rows >= n_rows
            cp16(&sx[buf][r][q * 4],               // are never consumed
                 &x[(size_t)row * IN_FEATS + t * BK + q * 4]);
        }
        // wk tile: 16 kword rows x 64 words = 256 x 16B, 1 per thread
        {
            int r   = tid >> 4;
            int c16 = tid & 15;
            cp16(&sw[buf][r][c16 * 4],
                 &wk[(size_t)(t * 16 + r) * OUT_FEATS + c16 * 4]);
        }
    };

    issue(0, 0);
    CP_COMMIT();

    for (int t = 0; t < IN_FEATS / BK; t++) {
        const int buf = t & 1;
        if (t + 1 < IN_FEATS / BK) {
            issue(t + 1, buf ^ 1);
            CP_COMMIT();
            CP_WAIT1();            // tile t resident; t+1 in flight
        } else {
            CP_WAIT0();
        }
        __syncthreads();

#pragma unroll
        for (int ks = 0; ks < 2; ks++) {
            const int kwb = ks * 8;

            unsigned a[2][4];
#pragma unroll
            for (int mt = 0; mt < 2; mt++) {
                int mrow = warp_m * 32 + mt * 16;
                float2 v;
                v = *(const float2*)&sx[buf][mrow + lq    ][2 * (kwb + lr)];
                a[mt][0] = pack_h2(v.x, v.y);
                v = *(const float2*)&sx[buf][mrow + lq + 8][2 * (kwb + lr)];
                a[mt][1] = pack_h2(v.x, v.y);
                v = *(const float2*)&sx[buf][mrow + lq    ][2 * (kwb + lr + 4)];
                a[mt][2] = pack_h2(v.x, v.y);
                v = *(const float2*)&sx[buf][mrow + lq + 8][2 * (kwb + lr + 4)];
                a[mt][3] = pack_h2(v.x, v.y);
            }
            unsigned b[4][2];
#pragma unroll
            for (int nt = 0; nt < 4; nt++) {
                int ncol = warp_n * 32 + nt * 8 + lq;
                b[nt][0] = sw[buf][kwb + lr    ][ncol];
                b[nt][1] = sw[buf][kwb + lr + 4][ncol];
            }

#pragma unroll
            for (int mt = 0; mt < 2; mt++)
#pragma unroll
                for (int nt = 0; nt < 4; nt++)
                    MMA_F16(acc[mt][nt], a[mt], b[nt]);
        }
        __syncthreads();
    }

    // epilogue: pack col pairs to half2
#pragma unroll
    for (int mt = 0; mt < 2; mt++) {
        int rbase = row0 + warp_m * 32 + mt * 16 + lq;
#pragma unroll
        for (int nt = 0; nt < 4; nt++) {
            int cp = warp_n * 16 + nt * 4 + lr;
            if (rbase < n_rows)
                h16[(size_t)rbase * H_PITCH + cp] =
                    pack_h2(acc[mt][nt][0], acc[mt][nt][1]);
            if (rbase + 8 < n_rows)
                h16[(size_t)(rbase + 8) * H_PITCH + cp] =
                    pack_h2(acc[mt][nt][2], acc[mt][nt][3]);
        }
    }
}

// ---------------------------------------------------------------------------
// Bucket build (standalone): hist + placement — atomic return IS the slot.
// Counters arrive all-zero (self-resetting invariant, see aggregate).
// ---------------------------------------------------------------------------
__global__ __launch_bounds__(256) void bucket_kernel(
    const int* __restrict__ src,
    const int* __restrict__ dst,
    const float* __restrict__ ew,
    int* __restrict__ count,
    int2* __restrict__ edge, int n_edges)
{
    int base = (blockIdx.x * blockDim.x + threadIdx.x) * 4;
    if (base + 3 < n_edges) {
        int4   s4 = *(const int4*)&src[base];
        int4   d4 = *(const int4*)&dst[base];
        float4 w4 = *(const float4*)&ew[base];
        int r0 = atomicAdd(&count[d4.x], 1);
        int r1 = atomicAdd(&count[d4.y], 1);
        int r2 = atomicAdd(&count[d4.z], 1);
        int r3 = atomicAdd(&count[d4.w], 1);
        if (r0 < CAP) edge[(size_t)d4.x * CAP + r0] = make_int2(s4.x, __float_as_int(w4.x));
        if (r1 < CAP) edge[(size_t)d4.y * CAP + r1] = make_int2(s4.y, __float_as_int(w4.y));
        if (r2 < CAP) edge[(size_t)d4.z * CAP + r2] = make_int2(s4.z, __float_as_int(w4.z));
        if (r3 < CAP) edge[(size_t)d4.w * CAP + r3] = make_int2(s4.w, __float_as_int(w4.w));
    } else {
        for (int i = base; i < n_edges; i++) {
            int d = dst[i];
            int r = atomicAdd(&count[d], 1);
            if (r < CAP)
                edge[(size_t)d * CAP + r] = make_int2(src[i], __float_as_int(ew[i]));
        }
    }
}

// ---------------------------------------------------------------------------
// Aggregate: quarter-warp per node; lane owns 8 feats (uint4 of h16).
// Per-quarter shfl masks; all <=8 edge chunks preloaded (MLP 8).
// Resets count[node] to 0 (restores invariant for next replay).
// ---------------------------------------------------------------------------
__global__ __launch_bounds__(256) void aggregate_kernel(
    const unsigned* __restrict__ h16,
    int* __restrict__ count,
    const int2* __restrict__ edge,
    const float* __restrict__ bias,
    float* __restrict__ out, int n_nodes)
{
    const int lane = threadIdx.x & 31;
    const int q    = lane >> 3;       // quarter (0..3)
    const int l8   = lane & 7;
    const int node = ((blockIdx.x * blockDim.x + threadIdx.x) >> 5) * 4 + q;
    if (node >= n_nodes) return;      // quarters diverge freely (qmask shfl)

    const unsigned qmask = 0xFFu << (q * 8);
    const size_t beg = (size_t)node * CAP;
    const int  cnt   = min(count[node], CAP);
    if (l8 == 0) count[node] = 0;     // self-reset for next replay

    int2 e[8];
#pragma unroll
    for (int c = 0; c < 8; c++) {
        int idx = c * 8 + l8;
        e[c] = (idx < cnt) ? edge[beg + idx] : make_int2(0, 0);
    }

    float2 a0 = make_float2(0.f, 0.f), a1 = make_float2(0.f, 0.f);
    float2 a2 = make_float2(0.f, 0.f), a3 = make_float2(0.f, 0.f);

    const unsigned* hrow = h16 + l8 * 4;

#pragma unroll
    for (int c = 0; c < 8; c++) {
        if (c * 8 >= cnt) break;
#pragma unroll
        for (int i = 0; i < 8; i++) {
            if (c * 8 + i >= cnt) break;
            int   si = __shfl_sync(qmask, e[c].x, q * 8 + i);
            float wi = __int_as_float(__shfl_sync(qmask, e[c].y, q * 8 + i));
            uint4 hu = *(const uint4*)&hrow[(size_t)si * H_PITCH];
            float2 h0 = __half22float2(*(__half2*)&hu.x);
            float2 h1 = __half22float2(*(__half2*)&hu.y);
            float2 h2 = __half22float2(*(__half2*)&hu.z);
            float2 h3 = __half22float2(*(__half2*)&hu.w);
            a0.x = fmaf(h0.x, wi, a0.x);  a0.y = fmaf(h0.y, wi, a0.y);
            a1.x = fmaf(h1.x, wi, a1.x);  a1.y = fmaf(h1.y, wi, a1.y);
            a2.x = fmaf(h2.x, wi, a2.x);  a2.y = fmaf(h2.y, wi, a2.y);
            a3.x = fmaf(h3.x, wi, a3.x);  a3.y = fmaf(h3.y, wi, a3.y);
        }
    }

    {
        float4 b0 = *(const float4*)&bias[l8 * 8];
        float4 b1 = *(const float4*)&bias[l8 * 8 + 4];
        float4 o0, o1;
        o0.x = fmaxf(a0.x + b0.x, 0.f);  o0.y = fmaxf(a0.y + b0.y, 0.f);
        o0.z = fmaxf(a1.x + b0.z, 0.f);  o0.w = fmaxf(a1.y + b0.w, 0.f);
        o1.x = fmaxf(a2.x + b1.x, 0.f);  o1.y = fmaxf(a2.y + b1.y, 0.f);
        o1.z = fmaxf(a3.x + b1.z, 0.f);  o1.w = fmaxf(a3.y + b1.w, 0.f);
        float* op = &out[(size_t)node * OUT_FEATS + l8 * 8];
        *(float4*)op       = o0;
        *(float4*)(op + 4) = o1;
    }
}

// ---------------------------------------------------------------------------
// Launch: wconvert -> GEMM -> bucket -> aggregate (single stream).
// ---------------------------------------------------------------------------
extern "C" void kernel_launch(void* const* d_in, const int* in_sizes, int n_in,
                              void* d_out, int out_size)
{
    const float* x    = (const float*)d_in[0];
    const int*   src  = (const int*)d_in[1];
    const int*   dst  = (const int*)d_in[2];
    const float* ew   = (const float*)d_in[3];
    const float* w    = (const float*)d_in[4];
    const float* bias = (const float*)d_in[5];
    float*       out  = (float*)d_out;

    const int n_nodes = in_sizes[0] / IN_FEATS;
    const int n_edges = in_sizes[1];

    unsigned* h16;   cudaGetSymbolAddress((void**)&h16,   g_h16);
    int*      count; cudaGetSymbolAddress((void**)&count, g_count);
    int2*     edge;  cudaGetSymbolAddress((void**)&edge,  g_edge);
    unsigned* wk;    cudaGetSymbolAddress((void**)&wk,    g_wk);

    // 1) pack W into kword-fp16 layout
    wconvert_kernel<<<32, 256>>>(w, wk);

    // 2) h16 = fp16(x @ W)  (cp.async-pipelined fp16 tensor-core GEMM)
    gemm_f16_kernel<<<(n_nodes + BM - 1) / BM, 256>>>(x, wk, h16, n_nodes);

    // 3) bucket build (counters all-zero by self-reset invariant)
    bucket_kernel<<<(n_edges / 4 + 255) / 256, 256>>>(src, dst, ew, count,
                                                      edge, n_edges);

    // 4) aggregate + bias + relu (4 nodes / warp) — also resets counters
    {
        int blocks = (n_nodes + 31) / 32;
        aggregate_kernel<<<blocks, 256>>>(h16, count, edge, bias,
                                          out, n_nodes);
    }
}